// round 4
// baseline (speedup 1.0000x reference)
#include <cuda_runtime.h>
#include <cuda_bf16.h>
#include <cstdint>

#define NROWS 50000
#define KNB   32
#define CDIM  128
#define TOPK  16

// ---------------- scratch (device globals; no allocation) ----------------
__device__ __align__(16) float g_M [CDIM * CDIM];     // Wq^T @ Wk
__device__ __align__(16) float g_Ws[CDIM * CDIM];     // triu(W) + triu(W)^T
__device__ __align__(16) float g_qM[(size_t)NROWS * CDIM];  // feat @ M
__device__ __align__(16) float g_fW[(size_t)NROWS * CDIM];  // feat @ Ws
__device__ __align__(16) float g_scores[(size_t)NROWS * KNB];
__device__ int g_colmask[KNB];
__device__ int g_needfix;
__device__ int g_mask_narrow;   // 1 -> mask elements are 1 byte; 0 -> 4 bytes

// ---------------- K0: prep M, Ws, reset colmask/flags ----------------
__global__ void prep_kernel(const float* __restrict__ Wq,
                            const float* __restrict__ Wk,
                            const float* __restrict__ W) {
    int c = blockIdx.x;    // 0..127
    int e = threadIdx.x;   // 0..127
    float acc = 0.f;
#pragma unroll 8
    for (int d = 0; d < CDIM; d++)
        acc += Wq[d * CDIM + c] * Wk[d * CDIM + e];
    g_M[c * CDIM + e] = acc;

    // W_sym[i][j]: i<j -> W[i][j]; i>j -> W[j][i]; i==j -> 2*W[i][i]
    float w = (c <= e) ? W[c * CDIM + e] : W[e * CDIM + c];
    g_Ws[c * CDIM + e] = (c == e) ? 2.f * w : w;

    if (c == 0 && e < KNB) g_colmask[e] = 0;
    if (c == 0 && e == KNB) g_needfix = 0;
    if (c == 0 && e == KNB + 1) g_mask_narrow = 0;
}

// ---------------- K0b: sniff knn_mask element width ----------------
// Reads the first N*K/4 32-bit words (always within the buffer for any dtype).
// bool->int32 data: words in {0,1}. bool->float32: words in {0, 0x3F800000}.
// bool kept as 1-byte: words are byte-packed {0,1} patterns (e.g. 0x01010101),
// which fall outside the wide sets -> classified narrow.
__global__ void sniff_kernel(const unsigned int* __restrict__ w) {
    const int nwords = NROWS * KNB / 4;
    int bad = 0;
    for (int i = blockIdx.x * blockDim.x + threadIdx.x; i < nwords;
         i += gridDim.x * blockDim.x) {
        unsigned int v = w[i];
        if (v != 0u && v != 1u && v != 0x3F800000u) bad = 1;
    }
    if (bad) g_mask_narrow = 1;   // idempotent plain store
}

// ---------------- K1: SGEMM  [N,128] @ [128,128] -> scratch ----------------
// gridDim.y: 0 -> B=g_M, Out=g_qM ; 1 -> B=g_Ws, Out=g_fW
__global__ void __launch_bounds__(256, 2) gemm_kernel(const float* __restrict__ A) {
    const float* __restrict__ B   = blockIdx.y ? g_Ws : g_M;
    float*       __restrict__ Out = blockIdx.y ? g_fW : g_qM;

    extern __shared__ float sm[];
    float* As = sm;              // [64][128]  32 KB
    float* Bs = sm + 64 * 128;   // [128][128] 64 KB

    int tid  = threadIdx.x;
    int row0 = blockIdx.x * 64;

    for (int i = tid; i < 64 * 32; i += 256) {       // i indexes float4
        int r = i >> 5;
        float4 v = make_float4(0.f, 0.f, 0.f, 0.f);
        if (row0 + r < NROWS)
            v = reinterpret_cast<const float4*>(A)[(size_t)(row0 + r) * 32 + (i & 31)];
        reinterpret_cast<float4*>(As)[i] = v;
    }
    for (int i = tid; i < 128 * 32; i += 256)
        reinterpret_cast<float4*>(Bs)[i] = reinterpret_cast<const float4*>(B)[i];
    __syncthreads();

    int tx = tid & 15;   // cols tx*8 .. tx*8+7
    int ty = tid >> 4;   // rows ty*4 .. ty*4+3
    float acc[4][8];
#pragma unroll
    for (int i = 0; i < 4; i++)
#pragma unroll
        for (int j = 0; j < 8; j++) acc[i][j] = 0.f;

#pragma unroll 8
    for (int k = 0; k < 128; k++) {
        float a[4];
#pragma unroll
        for (int i = 0; i < 4; i++) a[i] = As[(ty * 4 + i) * 128 + k];
        float4 b0 = reinterpret_cast<const float4*>(Bs + k * 128 + tx * 8)[0];
        float4 b1 = reinterpret_cast<const float4*>(Bs + k * 128 + tx * 8)[1];
        float b[8] = {b0.x, b0.y, b0.z, b0.w, b1.x, b1.y, b1.z, b1.w};
#pragma unroll
        for (int i = 0; i < 4; i++)
#pragma unroll
            for (int j = 0; j < 8; j++) acc[i][j] += a[i] * b[j];
    }

#pragma unroll
    for (int i = 0; i < 4; i++) {
        int r = row0 + ty * 4 + i;
        if (r < NROWS) {
            float4 v0 = make_float4(acc[i][0], acc[i][1], acc[i][2], acc[i][3]);
            float4 v1 = make_float4(acc[i][4], acc[i][5], acc[i][6], acc[i][7]);
            float4* p = reinterpret_cast<float4*>(Out + (size_t)r * 128 + tx * 8);
            p[0] = v0; p[1] = v1;
        }
    }
}

// ---------------- K2: fused streaming kernel (one block per row) ----------------
__global__ void __launch_bounds__(128) main_kernel(
    const float* __restrict__ feat, const float* __restrict__ knn_xyz,
    const float* __restrict__ knn_feat, const void* __restrict__ knn_mask,
    float* __restrict__ out_xyz, float* __restrict__ out_att, float* __restrict__ out_ml)
{
    __shared__ __align__(16) float kfS[KNB * CDIM];   // 16 KB staged tile
    __shared__ __align__(16) float qMS[CDIM];
    __shared__ __align__(16) float fWS[CDIM];
    __shared__ float xyzS[KNB * 3];
    __shared__ float scS[KNB], mlS[KNB], attnS[KNB];
    __shared__ float redS[4];
    __shared__ int   narrowS;

    int n    = blockIdx.x;
    int tid  = threadIdx.x;
    int lane = tid & 31;
    int warp = tid >> 5;

    qMS[tid] = g_qM[(size_t)n * CDIM + tid];
    fWS[tid] = g_fW[(size_t)n * CDIM + tid];
    if (tid < KNB * 3) xyzS[tid] = knn_xyz[(size_t)n * (KNB * 3) + tid];
    if (tid == 0) narrowS = g_mask_narrow;
    __syncthreads();

    float4 qv = reinterpret_cast<const float4*>(qMS)[lane];
    float4 fv = reinterpret_cast<const float4*>(fWS)[lane];
    int narrow = narrowS;

    // phase 1: warp w handles neighbors j = 8w .. 8w+7
    const float4* kf4 = reinterpret_cast<const float4*>(knn_feat + (size_t)n * (KNB * CDIM));
    int j0 = warp * 8;
    float4 kf[8];
#pragma unroll
    for (int jj = 0; jj < 8; jj++)
        kf[jj] = kf4[(j0 + jj) * 32 + lane];

#pragma unroll
    for (int jj = 0; jj < 8; jj++) {
        int j = j0 + jj;
        reinterpret_cast<float4*>(kfS + j * CDIM)[lane] = kf[jj];
        float s  = kf[jj].x * qv.x + kf[jj].y * qv.y + kf[jj].z * qv.z + kf[jj].w * qv.w;
        float ml = kf[jj].x * fv.x + kf[jj].y * fv.y + kf[jj].z * fv.z + kf[jj].w * fv.w;
#pragma unroll
        for (int o = 16; o; o >>= 1) {
            s  += __shfl_xor_sync(0xffffffffu, s,  o);
            ml += __shfl_xor_sync(0xffffffffu, ml, o);
        }
        if (lane == 0) {
            bool mvalid;
            if (narrow)
                mvalid = ((const unsigned char*)knn_mask)[(size_t)n * KNB + j] != 0;
            else
                mvalid = ((const unsigned int*)knn_mask)[(size_t)n * KNB + j] != 0u;
            if (!mvalid) s -= 1e12f;
            scS[j] = s;
            mlS[j] = ml;
        }
    }
    __syncthreads();

    // phase 2: topk rank + colmask mark + optimistic softmax (warp 0)
    if (tid < KNB) {
        float sj = scS[tid];
        int rank = 0;
#pragma unroll
        for (int i = 0; i < KNB; i++) {
            float si = scS[i];
            rank += (si > sj) || (si == sj && i < tid);  // lax.top_k stable tie rule
        }
        if (rank < TOPK) {
            if (__ldcg(&g_colmask[tid]) == 0) atomicOr(&g_colmask[tid], 1);
        }
        g_scores[(size_t)n * KNB + tid] = sj;
        out_ml[(size_t)n * KNB + tid]   = mlS[tid];

        float m = sj;
#pragma unroll
        for (int o = 16; o; o >>= 1) m = fmaxf(m, __shfl_xor_sync(0xffffffffu, m, o));
        float e = __expf(sj - m);
        float ssum = e;
#pragma unroll
        for (int o = 16; o; o >>= 1) ssum += __shfl_xor_sync(0xffffffffu, ssum, o);
        attnS[tid] = e / ssum;
    }
    __syncthreads();

    // phase 3: weighted sums + outputs (optimistic: col_mask == all zero)
    float acc = 0.f;
#pragma unroll
    for (int j = 0; j < KNB; j++)
        acc += attnS[j] * kfS[j * CDIM + tid];

    float fc = feat[(size_t)n * CDIM + tid];
    size_t ob = (size_t)n * 257;
    out_att[ob + tid]        = fc;    // attentive_feats[:, 0:128] = feat
    out_att[ob + 128 + tid]  = acc;   // attentive_feats[:, 128:256] = corres_feat

    float p = fWS[tid] * acc;
#pragma unroll
    for (int o = 16; o; o >>= 1) p += __shfl_xor_sync(0xffffffffu, p, o);
    if (lane == 0) redS[warp] = p;
    __syncthreads();
    if (tid == 0) out_att[ob + 256] = redS[0] + redS[1] + redS[2] + redS[3];  // logit

    if (tid < 3) {
        float x = 0.f;
#pragma unroll
        for (int j = 0; j < KNB; j++) x += attnS[j] * xyzS[j * 3 + tid];
        out_xyz[(size_t)n * 3 + tid] = x;
    }
}

// ---------------- K3: check whether any column never made top-k ----------------
__global__ void check_kernel() {
    int nf = 0;
    for (int j = 0; j < KNB; j++) nf |= (g_colmask[j] == 0);
    g_needfix = nf;
}

// ---------------- K4: fixup (early-exits when colmask is all-covered) ----------------
__global__ void __launch_bounds__(128) fixup_kernel(
    const float* __restrict__ knn_feat, const float* __restrict__ knn_xyz,
    float* __restrict__ out_xyz, float* __restrict__ out_att)
{
    if (g_needfix == 0) return;   // the common case: nothing to do

    __shared__ float attnS[KNB];
    __shared__ float redS[4];
    __shared__ int   colS[KNB];
    int tid = threadIdx.x, lane = tid & 31, warp = tid >> 5;
    if (tid < KNB) colS[tid] = g_colmask[tid];
    __syncthreads();

    for (int n = blockIdx.x; n < NROWS; n += gridDim.x) {
        if (tid < KNB) {
            float s  = g_scores[(size_t)n * KNB + tid];
            int inc  = colS[tid];
            float se = inc ? s : -3.0e38f;
            float m = se;
#pragma unroll
            for (int o = 16; o; o >>= 1) m = fmaxf(m, __shfl_xor_sync(0xffffffffu, m, o));
            float e = inc ? __expf(se - m) : 0.f;
            float ssum = e;
#pragma unroll
            for (int o = 16; o; o >>= 1) ssum += __shfl_xor_sync(0xffffffffu, ssum, o);
            attnS[tid] = e / ssum;
        }
        __syncthreads();

        float acc = 0.f;
#pragma unroll
        for (int j = 0; j < KNB; j++)
            acc += attnS[j] * knn_feat[(size_t)n * (KNB * CDIM) + j * CDIM + tid];

        size_t ob = (size_t)n * 257;
        out_att[ob + 128 + tid] = acc;

        float p = g_fW[(size_t)n * CDIM + tid] * acc;
#pragma unroll
        for (int o = 16; o; o >>= 1) p += __shfl_xor_sync(0xffffffffu, p, o);
        if (lane == 0) redS[warp] = p;
        __syncthreads();
        if (tid == 0) out_att[ob + 256] = redS[0] + redS[1] + redS[2] + redS[3];

        if (tid < 3) {
            float x = 0.f;
#pragma unroll
            for (int j = 0; j < KNB; j++)
                x += attnS[j] * knn_xyz[(size_t)n * (KNB * 3) + j * 3 + tid];
            out_xyz[(size_t)n * 3 + tid] = x;
        }
        __syncthreads();
    }
}

// ---------------- launch ----------------
extern "C" void kernel_launch(void* const* d_in, const int* in_sizes, int n_in,
                              void* d_out, int out_size) {
    const float* feat     = (const float*)d_in[0];          // [N,128]
    const float* knn_xyz  = (const float*)d_in[1];          // [N,32,3]
    const float* knn_feat = (const float*)d_in[2];          // [N,32,128]
    const void*  knn_mask = d_in[3];                        // [N,32] bool (width sniffed)
    const float* Wq       = (const float*)d_in[4];          // [128,128]
    const float* Wk       = (const float*)d_in[5];          // [128,128]
    const float* W        = (const float*)d_in[6];          // [128,128]

    float* out     = (float*)d_out;
    float* out_xyz = out;                                   // [N,3]
    float* out_att = out + (size_t)NROWS * 3;               // [N,257]
    float* out_ml  = out + (size_t)NROWS * 3 + (size_t)NROWS * 257;  // [N,32]

    prep_kernel<<<CDIM, CDIM>>>(Wq, Wk, W);
    sniff_kernel<<<512, 256>>>((const unsigned int*)knn_mask);

    cudaFuncSetAttribute(gemm_kernel, cudaFuncAttributeMaxDynamicSharedMemorySize, 98304);
    gemm_kernel<<<dim3((NROWS + 63) / 64, 2), 256, 98304>>>(feat);

    main_kernel<<<NROWS, CDIM>>>(feat, knn_xyz, knn_feat, knn_mask,
                                 out_xyz, out_att, out_ml);

    check_kernel<<<1, 1>>>();
    fixup_kernel<<<2048, CDIM>>>(knn_feat, knn_xyz, out_xyz, out_att);
}

// round 5
// speedup vs baseline: 1.0148x; 1.0148x over previous
#include <cuda_runtime.h>
#include <cuda_bf16.h>
#include <cstdint>

#define NROWS 50000
#define KNB   32
#define CDIM  128
#define TOPK  16

// ---------------- scratch (device globals; no allocation) ----------------
__device__ __align__(16) float g_M [CDIM * CDIM];     // Wq^T @ Wk
__device__ __align__(16) float g_Ws[CDIM * CDIM];     // triu(W) + triu(W)^T
__device__ __align__(16) float g_qM[(size_t)NROWS * CDIM];  // feat @ M
__device__ __align__(16) float g_fW[(size_t)NROWS * CDIM];  // feat @ Ws
__device__ __align__(16) float g_scores[(size_t)NROWS * KNB];
__device__ int g_colmask[KNB];
__device__ int g_needfix;
__device__ int g_mask_narrow;   // 1 -> mask elements are 1 byte; 0 -> 4 bytes

// ---------------- cp.async helpers ----------------
__device__ __forceinline__ void cp_async16(void* smem_dst, const void* gptr) {
    uint32_t s = (uint32_t)__cvta_generic_to_shared(smem_dst);
    asm volatile("cp.async.cg.shared.global [%0], [%1], 16;\n" :: "r"(s), "l"(gptr));
}
__device__ __forceinline__ void cp_async_commit() {
    asm volatile("cp.async.commit_group;\n" ::: "memory");
}
__device__ __forceinline__ void cp_async_wait_all() {
    asm volatile("cp.async.wait_group 0;\n" ::: "memory");
}

// ---------------- K0: prep M, Ws, reset colmask/flags ----------------
__global__ void prep_kernel(const float* __restrict__ Wq,
                            const float* __restrict__ Wk,
                            const float* __restrict__ W) {
    int c = blockIdx.x;    // 0..127
    int e = threadIdx.x;   // 0..127
    float acc = 0.f;
#pragma unroll 8
    for (int d = 0; d < CDIM; d++)
        acc += Wq[d * CDIM + c] * Wk[d * CDIM + e];
    g_M[c * CDIM + e] = acc;

    float w = (c <= e) ? W[c * CDIM + e] : W[e * CDIM + c];
    g_Ws[c * CDIM + e] = (c == e) ? 2.f * w : w;

    if (c == 0 && e < KNB) g_colmask[e] = 0;
    if (c == 0 && e == KNB) g_needfix = 0;
    if (c == 0 && e == KNB + 1) g_mask_narrow = 0;
}

// ---------------- K0b: sniff knn_mask element width ----------------
__global__ void sniff_kernel(const unsigned int* __restrict__ w) {
    const int nwords = NROWS * KNB / 4;
    int bad = 0;
    for (int i = blockIdx.x * blockDim.x + threadIdx.x; i < nwords;
         i += gridDim.x * blockDim.x) {
        unsigned int v = w[i];
        if (v != 0u && v != 1u && v != 0x3F800000u) bad = 1;
    }
    if (bad) g_mask_narrow = 1;
}

// ---------------- K1: dual-output SGEMM  [N,128]@[128,128] x2 ----------------
// One block: 64 rows, computes BOTH feat@M -> g_qM and feat@Ws -> g_fW,
// sharing the A tile (one A read). smem: As 32K + BsM 64K + BsW 64K = 160K.
__global__ void __launch_bounds__(256, 1) gemm_kernel(const float* __restrict__ A) {
    extern __shared__ float sm[];
    float* As  = sm;                 // [64][128]
    float* BsM = sm + 64 * 128;      // [128][128]
    float* BsW = BsM + 128 * 128;    // [128][128]

    int tid  = threadIdx.x;
    int row0 = blockIdx.x * 64;

    for (int i = tid; i < 64 * 32; i += 256) {       // float4 index
        int r = i >> 5;
        float4 v = make_float4(0.f, 0.f, 0.f, 0.f);
        if (row0 + r < NROWS)
            v = reinterpret_cast<const float4*>(A)[(size_t)(row0 + r) * 32 + (i & 31)];
        reinterpret_cast<float4*>(As)[i] = v;
    }
    for (int i = tid; i < 128 * 32; i += 256) {
        reinterpret_cast<float4*>(BsM)[i] = reinterpret_cast<const float4*>(g_M)[i];
        reinterpret_cast<float4*>(BsW)[i] = reinterpret_cast<const float4*>(g_Ws)[i];
    }
    __syncthreads();

    int tx = tid & 15;   // cols tx*8 .. tx*8+7
    int ty = tid >> 4;   // rows ty*4 .. ty*4+3
    float accM[4][8], accW[4][8];
#pragma unroll
    for (int i = 0; i < 4; i++)
#pragma unroll
        for (int j = 0; j < 8; j++) { accM[i][j] = 0.f; accW[i][j] = 0.f; }

#pragma unroll 4
    for (int k = 0; k < 128; k++) {
        float a[4];
#pragma unroll
        for (int i = 0; i < 4; i++) a[i] = As[(ty * 4 + i) * 128 + k];
        float4 m0 = reinterpret_cast<const float4*>(BsM + k * 128 + tx * 8)[0];
        float4 m1 = reinterpret_cast<const float4*>(BsM + k * 128 + tx * 8)[1];
        float4 w0 = reinterpret_cast<const float4*>(BsW + k * 128 + tx * 8)[0];
        float4 w1 = reinterpret_cast<const float4*>(BsW + k * 128 + tx * 8)[1];
        float bm[8] = {m0.x, m0.y, m0.z, m0.w, m1.x, m1.y, m1.z, m1.w};
        float bw[8] = {w0.x, w0.y, w0.z, w0.w, w1.x, w1.y, w1.z, w1.w};
#pragma unroll
        for (int i = 0; i < 4; i++)
#pragma unroll
            for (int j = 0; j < 8; j++) {
                accM[i][j] += a[i] * bm[j];
                accW[i][j] += a[i] * bw[j];
            }
    }

#pragma unroll
    for (int i = 0; i < 4; i++) {
        int r = row0 + ty * 4 + i;
        if (r < NROWS) {
            float4* pq = reinterpret_cast<float4*>(g_qM + (size_t)r * 128 + tx * 8);
            float4* pf = reinterpret_cast<float4*>(g_fW + (size_t)r * 128 + tx * 8);
            pq[0] = make_float4(accM[i][0], accM[i][1], accM[i][2], accM[i][3]);
            pq[1] = make_float4(accM[i][4], accM[i][5], accM[i][6], accM[i][7]);
            pf[0] = make_float4(accW[i][0], accW[i][1], accW[i][2], accW[i][3]);
            pf[1] = make_float4(accW[i][4], accW[i][5], accW[i][6], accW[i][7]);
        }
    }
}

// ---------------- K2: fused streaming kernel (one block per row) ----------------
__global__ void __launch_bounds__(128, 10) main_kernel(
    const float* __restrict__ feat, const float* __restrict__ knn_xyz,
    const float* __restrict__ knn_feat, const void* __restrict__ knn_mask,
    float* __restrict__ out_xyz, float* __restrict__ out_att, float* __restrict__ out_ml)
{
    __shared__ __align__(16) float kfS[KNB * CDIM];   // 16 KB, filled by cp.async
    __shared__ __align__(16) float qMS[CDIM];
    __shared__ __align__(16) float fWS[CDIM];
    __shared__ float xyzS[KNB * 3];
    __shared__ float maskAdjS[KNB];                   // 0 or -1e12
    __shared__ float scS[KNB], mlS[KNB], attnS[KNB];
    __shared__ float redS[4];

    int n    = blockIdx.x;
    int tid  = threadIdx.x;
    int lane = tid & 31;
    int warp = tid >> 5;

    // kick off bulk knn_feat load first (global -> smem, bypass L1)
    {
        float4*       dst = reinterpret_cast<float4*>(kfS);
        const float4* src = reinterpret_cast<const float4*>(knn_feat + (size_t)n * (KNB * CDIM));
#pragma unroll
        for (int i = 0; i < 8; i++)
            cp_async16(dst + i * 128 + tid, src + i * 128 + tid);
        cp_async_commit();
    }

    // overlapped small loads
    float fc = __ldg(&feat[(size_t)n * CDIM + tid]);   // used only at the end
    qMS[tid] = g_qM[(size_t)n * CDIM + tid];
    fWS[tid] = g_fW[(size_t)n * CDIM + tid];
    if (tid < KNB * 3) xyzS[tid] = knn_xyz[(size_t)n * (KNB * 3) + tid];
    if (tid < KNB) {
        bool mvalid;
        if (g_mask_narrow)
            mvalid = ((const unsigned char*)knn_mask)[(size_t)n * KNB + tid] != 0;
        else
            mvalid = ((const unsigned int*)knn_mask)[(size_t)n * KNB + tid] != 0u;
        maskAdjS[tid] = mvalid ? 0.f : -1e12f;
    }
    cp_async_wait_all();
    __syncthreads();

    float4 qv = reinterpret_cast<const float4*>(qMS)[lane];
    float4 fv = reinterpret_cast<const float4*>(fWS)[lane];

    // dots: warp w handles neighbors 8w..8w+7; batched partials then
    // level-interleaved butterflies (independent shuffles per level).
    int j0 = warp * 8;
    float s[8], ml[8];
#pragma unroll
    for (int jj = 0; jj < 8; jj++) {
        float4 kf = reinterpret_cast<const float4*>(kfS + (j0 + jj) * CDIM)[lane];
        s [jj] = kf.x * qv.x + kf.y * qv.y + kf.z * qv.z + kf.w * qv.w;
        ml[jj] = kf.x * fv.x + kf.y * fv.y + kf.z * fv.z + kf.w * fv.w;
    }
#pragma unroll
    for (int o = 16; o; o >>= 1) {
#pragma unroll
        for (int jj = 0; jj < 8; jj++) {
            s [jj] += __shfl_xor_sync(0xffffffffu, s [jj], o);
            ml[jj] += __shfl_xor_sync(0xffffffffu, ml[jj], o);
        }
    }
#pragma unroll
    for (int jj = 0; jj < 8; jj++) {
        if (lane == jj) {
            scS[j0 + jj] = s[jj] + maskAdjS[j0 + jj];
            mlS[j0 + jj] = ml[jj];
        }
    }
    __syncthreads();

    // topk rank + colmask mark + optimistic softmax (warp 0)
    if (tid < KNB) {
        float sj = scS[tid];
        int rank = 0;
#pragma unroll
        for (int i = 0; i < KNB; i++) {
            float si = scS[i];
            rank += (si > sj) || (si == sj && i < tid);  // lax.top_k stable tie rule
        }
        if (rank < TOPK) {
            if (__ldcg(&g_colmask[tid]) == 0) atomicOr(&g_colmask[tid], 1);
        }
        g_scores[(size_t)n * KNB + tid] = sj;
        out_ml[(size_t)n * KNB + tid]   = mlS[tid];

        float m = sj;
#pragma unroll
        for (int o = 16; o; o >>= 1) m = fmaxf(m, __shfl_xor_sync(0xffffffffu, m, o));
        float e = __expf(sj - m);
        float ssum = e;
#pragma unroll
        for (int o = 16; o; o >>= 1) ssum += __shfl_xor_sync(0xffffffffu, ssum, o);
        attnS[tid] = e / ssum;
    }
    __syncthreads();

    // weighted sums + outputs (optimistic: col_mask == all zero)
    float a0 = 0.f, a1 = 0.f, a2 = 0.f, a3 = 0.f;
#pragma unroll
    for (int j = 0; j < KNB; j += 4) {
        a0 += attnS[j    ] * kfS[(j    ) * CDIM + tid];
        a1 += attnS[j + 1] * kfS[(j + 1) * CDIM + tid];
        a2 += attnS[j + 2] * kfS[(j + 2) * CDIM + tid];
        a3 += attnS[j + 3] * kfS[(j + 3) * CDIM + tid];
    }
    float acc = (a0 + a1) + (a2 + a3);

    size_t ob = (size_t)n * 257;
    out_att[ob + tid]       = fc;    // attentive_feats[:, 0:128] = feat
    out_att[ob + 128 + tid] = acc;   // attentive_feats[:, 128:256] = corres_feat

    float p = fWS[tid] * acc;
#pragma unroll
    for (int o = 16; o; o >>= 1) p += __shfl_xor_sync(0xffffffffu, p, o);
    if (lane == 0) redS[warp] = p;
    __syncthreads();
    if (tid == 0) out_att[ob + 256] = redS[0] + redS[1] + redS[2] + redS[3];  // logit

    if (tid < 3) {
        float x = 0.f;
#pragma unroll
        for (int j = 0; j < KNB; j++) x += attnS[j] * xyzS[j * 3 + tid];
        out_xyz[(size_t)n * 3 + tid] = x;
    }
}

// ---------------- K3: check whether any column never made top-k ----------------
__global__ void check_kernel() {
    int nf = 0;
    for (int j = 0; j < KNB; j++) nf |= (g_colmask[j] == 0);
    g_needfix = nf;
}

// ---------------- K4: fixup (early-exits when colmask is all-covered) ----------------
__global__ void __launch_bounds__(128) fixup_kernel(
    const float* __restrict__ knn_feat, const float* __restrict__ knn_xyz,
    float* __restrict__ out_xyz, float* __restrict__ out_att)
{
    if (g_needfix == 0) return;   // the common case: nothing to do

    __shared__ float attnS[KNB];
    __shared__ float redS[4];
    __shared__ int   colS[KNB];
    int tid = threadIdx.x, lane = tid & 31, warp = tid >> 5;
    if (tid < KNB) colS[tid] = g_colmask[tid];
    __syncthreads();

    for (int n = blockIdx.x; n < NROWS; n += gridDim.x) {
        if (tid < KNB) {
            float s  = g_scores[(size_t)n * KNB + tid];
            int inc  = colS[tid];
            float se = inc ? s : -3.0e38f;
            float m = se;
#pragma unroll
            for (int o = 16; o; o >>= 1) m = fmaxf(m, __shfl_xor_sync(0xffffffffu, m, o));
            float e = inc ? __expf(se - m) : 0.f;
            float ssum = e;
#pragma unroll
            for (int o = 16; o; o >>= 1) ssum += __shfl_xor_sync(0xffffffffu, ssum, o);
            attnS[tid] = e / ssum;
        }
        __syncthreads();

        float acc = 0.f;
#pragma unroll
        for (int j = 0; j < KNB; j++)
            acc += attnS[j] * knn_feat[(size_t)n * (KNB * CDIM) + j * CDIM + tid];

        size_t ob = (size_t)n * 257;
        out_att[ob + 128 + tid] = acc;

        float p = g_fW[(size_t)n * CDIM + tid] * acc;
#pragma unroll
        for (int o = 16; o; o >>= 1) p += __shfl_xor_sync(0xffffffffu, p, o);
        if (lane == 0) redS[warp] = p;
        __syncthreads();
        if (tid == 0) out_att[ob + 256] = redS[0] + redS[1] + redS[2] + redS[3];

        if (tid < 3) {
            float x = 0.f;
#pragma unroll
            for (int j = 0; j < KNB; j++)
                x += attnS[j] * knn_xyz[(size_t)n * (KNB * 3) + j * 3 + tid];
            out_xyz[(size_t)n * 3 + tid] = x;
        }
        __syncthreads();
    }
}

// ---------------- launch ----------------
extern "C" void kernel_launch(void* const* d_in, const int* in_sizes, int n_in,
                              void* d_out, int out_size) {
    const float* feat     = (const float*)d_in[0];          // [N,128]
    const float* knn_xyz  = (const float*)d_in[1];          // [N,32,3]
    const float* knn_feat = (const float*)d_in[2];          // [N,32,128]
    const void*  knn_mask = d_in[3];                        // [N,32] bool (width sniffed)
    const float* Wq       = (const float*)d_in[4];          // [128,128]
    const float* Wk       = (const float*)d_in[5];          // [128,128]
    const float* W        = (const float*)d_in[6];          // [128,128]

    float* out     = (float*)d_out;
    float* out_xyz = out;                                   // [N,3]
    float* out_att = out + (size_t)NROWS * 3;               // [N,257]
    float* out_ml  = out + (size_t)NROWS * 3 + (size_t)NROWS * 257;  // [N,32]

    prep_kernel<<<CDIM, CDIM>>>(Wq, Wk, W);
    sniff_kernel<<<512, 256>>>((const unsigned int*)knn_mask);

    cudaFuncSetAttribute(gemm_kernel, cudaFuncAttributeMaxDynamicSharedMemorySize, 163840);
    gemm_kernel<<<(NROWS + 63) / 64, 256, 163840>>>(feat);

    main_kernel<<<NROWS, CDIM>>>(feat, knn_xyz, knn_feat, knn_mask,
                                 out_xyz, out_att, out_ml);

    check_kernel<<<1, 1>>>();
    fixup_kernel<<<2048, CDIM>>>(knn_feat, knn_xyz, out_xyz, out_att);
}